// round 17
// baseline (speedup 1.0000x reference)
#include <cuda_runtime.h>
#include <math.h>

#define KS        11
#define HALO      5
#define OT        64                 // output tile (square)
#define IN_T      (OT + 2*HALO)      // 74 input tile
#define IMG       512
#define SIN_PITCH (IN_T + 2)         // 76 floats: %4==0 (float4-aligned), not %32

__device__ __forceinline__ int reflect_idx(int i) {
    if (i < 0)     return -i;
    if (i >= IMG)  return 2*IMG - 2 - i;
    return i;
}

__global__ __launch_bounds__(256, 6)
void gaussian_blur_kernel(const float* __restrict__ x,
                          const float* __restrict__ sigma,
                          float* __restrict__ out)
{
    // Single tile buffer: raw input (74x74, pitched 76); horizontal pass
    // overwrites cols [0,64) of each row in place.
    __shared__ float s_in[IN_T][SIN_PITCH];

    const int tid = threadIdx.y * 32 + threadIdx.x;   // 0..255
    const int tx  = threadIdx.x;
    const int ty  = threadIdx.y;

    // ---- 1D normalized Gaussian weights (separable == reference 2D kernel) ----
    float w[KS];
    {
        const float s   = fabsf(sigma[0]) + 1e-6f;
        const float inv = 1.0f / (2.0f * s * s);
        float sum = 0.0f;
        #pragma unroll
        for (int k = 0; k < KS; ++k) {
            const float r = (float)k - (float)HALO;
            w[k] = expf(-r * r * inv);
            sum += w[k];
        }
        const float rs = 1.0f / sum;
        #pragma unroll
        for (int k = 0; k < KS; ++k) w[k] *= rs;
    }

    const long long plane = blockIdx.z;                 // b*C + c, 0..1023
    const float* __restrict__ xp = x   + plane * (long long)(IMG * IMG);
    float*       __restrict__ op = out + plane * (long long)(IMG * IMG);

    const int tile_x = blockIdx.x * OT;
    const int tile_y = blockIdx.y * OT;

    // ---- load 74x74 input tile with reflect padding ----
    #pragma unroll
    for (int r = ty; r < IN_T; r += 8) {
        const int gy = reflect_idx(tile_y + r - HALO);
        const float* __restrict__ row = xp + (long long)gy * IMG;
        #pragma unroll
        for (int c = tx; c < IN_T; c += 32) {
            const int gx = reflect_idx(tile_x + c - HALO);
            s_in[r][c] = row[gx];
        }
    }
    __syncthreads();

    // ---- horizontal pass, IN PLACE: 8 outputs/thread per row ----
    // Row r owned by the 8 lanes with tid>>3 == (row index mod 32 mapping);
    // those 8 lanes are contiguous in one warp, so an 8-lane __syncwarp
    // orders "all reads of row r" before "writes to row r".
    {
        const int c8   = (tid & 7) * 8;                 // 0,8,...,56
        const unsigned row_mask = 0xFFu << ((tid & 31) & 24);  // my 8-lane row group
        for (int r = tid >> 3; r < IN_T; r += 32) {
            float acc[8];
            #pragma unroll
            for (int m = 0; m < 8; ++m) acc[m] = 0.0f;

            // stream 5 float4 chunks covering window cols c8 .. c8+19
            #pragma unroll
            for (int cj = 0; cj < 5; ++cj) {
                const float4 v = *(const float4*)&s_in[r][c8 + 4*cj];
                const float vv[4] = { v.x, v.y, v.z, v.w };
                #pragma unroll
                for (int e = 0; e < 4; ++e) {
                    const int j = 4*cj + e;             // window index
                    #pragma unroll
                    for (int m = 0; m < 8; ++m) {
                        const int k = j - m;
                        if (k >= 0 && k < KS)
                            acc[m] = fmaf(w[k], vv[e], acc[m]);
                    }
                }
            }

            __syncwarp(row_mask);                       // reads done before in-place write
            float4 o0; o0.x = acc[0]; o0.y = acc[1]; o0.z = acc[2]; o0.w = acc[3];
            float4 o1; o1.x = acc[4]; o1.y = acc[5]; o1.z = acc[6]; o1.w = acc[7];
            *(float4*)&s_in[r][c8]     = o0;
            *(float4*)&s_in[r][c8 + 4] = o1;
        }
    }
    __syncthreads();

    // ---- vertical pass: thread owns 1 col x 8 output rows, 2 groups ----
    // Streams 18 scalar LDS per 8 outputs (9 B/out). Warp reads 32 consecutive
    // cols -> conflict-free; stores coalesced (32 x STG.32 = 128 B).
    {
        const int col = tid & 63;                       // 0..63
        const int rg  = tid >> 6;                       // 0..3
        #pragma unroll
        for (int g = 0; g < 2; ++g) {
            const int r0 = rg * 8 + g * 32;             // first output row of group
            float acc[8];
            #pragma unroll
            for (int m = 0; m < 8; ++m) acc[m] = 0.0f;

            #pragma unroll
            for (int j = 0; j < 18; ++j) {              // window rows r0 .. r0+17
                const float v = s_in[r0 + j][col];
                #pragma unroll
                for (int m = 0; m < 8; ++m) {
                    const int k = j - m;
                    if (k >= 0 && k < KS)
                        acc[m] = fmaf(w[k], v, acc[m]);
                }
            }

            float* __restrict__ obase = op + (long long)(tile_y + r0) * IMG + tile_x + col;
            #pragma unroll
            for (int m = 0; m < 8; ++m)
                obase[(long long)m * IMG] = acc[m];
        }
    }
}

extern "C" void kernel_launch(void* const* d_in, const int* in_sizes, int n_in,
                              void* d_out, int out_size)
{
    const float* x     = (const float*)d_in[0];   // (16,64,512,512) fp32
    const float* sigma = (const float*)d_in[1];   // (1,) fp32
    float* out = (float*)d_out;

    const int n_planes = in_sizes[0] / (IMG * IMG);   // 16*64 = 1024

    dim3 block(32, 8, 1);
    dim3 grid(IMG / OT, IMG / OT, n_planes);          // 8 x 8 x 1024
    gaussian_blur_kernel<<<grid, block>>>(x, sigma, out);
}